// round 2
// baseline (speedup 1.0000x reference)
#include <cuda_runtime.h>
#include <math.h>

#define NN 100000
#define EE 1600000

// Scratch (alloc-free: __device__ globals)
__device__ int   g_is64;
__device__ int   g_deg[NN];
__device__ float g_dinv[NN];
__device__ float g_bufT[(size_t)NN * 128];  // transformed features (x @ W)
__device__ float g_bufO[(size_t)NN * 128];  // aggregated output per layer

// ---------------- edge dtype detection ----------------
// int64 little-endian with values < 2^31: odd int32 words are all zero.
// int32: odd words are random node ids (all-zero chance ~0).
__global__ void k_detect(const void* __restrict__ ei) {
    if (threadIdx.x == 0 && blockIdx.x == 0) {
        const int* w = (const int*)ei;
        int nz = 0;
        for (int i = 1; i < 256; i += 2) nz += (w[i] != 0);
        g_is64 = (nz == 0) ? 1 : 0;
    }
}

__device__ __forceinline__ int edge_at(const void* __restrict__ ei, long long i) {
    if (g_is64) return (int)((const long long*)ei)[i];
    return ((const int*)ei)[i];
}

// ---------------- degree / norm ----------------
__global__ void k_init_deg() {
    int i = blockIdx.x * blockDim.x + threadIdx.x;
    if (i < NN) g_deg[i] = 1;  // self-loop
}

__global__ void k_count_deg(const void* __restrict__ ei) {
    int i = blockIdx.x * blockDim.x + threadIdx.x;
    if (i < EE) {
        int d = edge_at(ei, (long long)EE + i);
        atomicAdd(&g_deg[d], 1);
    }
}

__global__ void k_dinv() {
    int i = blockIdx.x * blockDim.x + threadIdx.x;
    if (i < NN) g_dinv[i] = rsqrtf((float)g_deg[i]);
}

// ---------------- dense transform: out[n,O] = X[n,K] @ W[K,O] ----------------
template <int K, int O>
__global__ void gemm_kernel(const float* __restrict__ X, const float* __restrict__ W,
                            float* __restrict__ out, int n) {
    constexpr int JG = O / 4;          // feature groups of 4
    constexpr int RQ = 256 / JG;       // row-quads per block
    constexpr int ROWS = RQ * 4;
    extern __shared__ float sm[];
    float* Ws = sm;                    // K*O
    float* Xs = sm + K * O;            // ROWS*K
    int tid = threadIdx.x;
    int row0 = blockIdx.x * ROWS;

    for (int i = tid * 4; i < K * O; i += 256 * 4)
        *(float4*)&Ws[i] = *(const float4*)&W[i];

    for (int i = tid * 4; i < ROWS * K; i += 256 * 4) {
        int r = i / K, c = i % K;
        float4 v = make_float4(0.f, 0.f, 0.f, 0.f);
        if (row0 + r < n) v = *(const float4*)&X[(size_t)(row0 + r) * K + c];
        *(float4*)&Xs[i] = v;
    }
    __syncthreads();

    int jg = tid % JG, rq = tid / JG;
    int j = jg * 4;
    float acc[4][4] = {};
    const float* xb = &Xs[(rq * 4) * K];
#pragma unroll 4
    for (int k = 0; k < K; k++) {
        float4 w = *(float4*)&Ws[k * O + j];
#pragma unroll
        for (int i = 0; i < 4; i++) {
            float xv = xb[i * K + k];
            acc[i][0] += xv * w.x;
            acc[i][1] += xv * w.y;
            acc[i][2] += xv * w.z;
            acc[i][3] += xv * w.w;
        }
    }
#pragma unroll
    for (int i = 0; i < 4; i++) {
        int r = row0 + rq * 4 + i;
        if (r < n)
            *(float4*)&out[(size_t)r * O + j] =
                make_float4(acc[i][0], acc[i][1], acc[i][2], acc[i][3]);
    }
}

// ---------------- self-loop init: O[v] = dinv[v]^2 * T[v] ----------------
template <int F>
__global__ void self_kernel(int n) {
    int idx = blockIdx.x * blockDim.x + threadIdx.x;  // over n*F/4
    if (idx >= n * (F / 4)) return;
    int v = idx / (F / 4);
    float d = g_dinv[v];
    float s = d * d;
    float4 t = *(const float4*)&g_bufT[(size_t)idx * 4];
    float4 o = make_float4(s * t.x, s * t.y, s * t.z, s * t.w);
    *(float4*)&g_bufO[(size_t)idx * 4] = o;
}

// ---------------- edge scatter: O[dst] += dinv[s]*dinv[d]*T[src] ----------------
template <int F>
__global__ void edge_kernel(const void* __restrict__ ei) {
    constexpr int QP = F / 4;
    long long idx = (long long)blockIdx.x * blockDim.x + threadIdx.x;
    if (idx >= (long long)EE * QP) return;
    int e = (int)(idx / QP);
    int q = (int)(idx % QP);
    int s = edge_at(ei, e);
    int d = edge_at(ei, (long long)EE + e);
    float nrm = g_dinv[s] * g_dinv[d];
    float4 t = *(const float4*)&g_bufT[(size_t)s * F + q * 4];
    float* po = &g_bufO[(size_t)d * F + q * 4];
    atomicAdd(po + 0, nrm * t.x);
    atomicAdd(po + 1, nrm * t.y);
    atomicAdd(po + 2, nrm * t.z);
    atomicAdd(po + 3, nrm * t.w);
}

// ---------------- bias + relu (in place on g_bufO) ----------------
template <int F>
__global__ void biasrelu_kernel(const float* __restrict__ b, int n) {
    int idx = blockIdx.x * blockDim.x + threadIdx.x;  // over n*F/4
    if (idx >= n * (F / 4)) return;
    int q = idx % (F / 4);
    float4 bv = *(const float4*)&b[q * 4];
    float4 o = *(float4*)&g_bufO[(size_t)idx * 4];
    o.x = fmaxf(o.x + bv.x, 0.f);
    o.y = fmaxf(o.y + bv.y, 0.f);
    o.z = fmaxf(o.z + bv.z, 0.f);
    o.w = fmaxf(o.w + bv.w, 0.f);
    *(float4*)&g_bufO[(size_t)idx * 4] = o;
}

// ---------------- head: sigmoid(H[n,32] @ Wl + bl) ----------------
__global__ void final_kernel(const float* __restrict__ Wl, const float* __restrict__ bl,
                             float* __restrict__ out, int n) {
    int v = blockIdx.x * blockDim.x + threadIdx.x;
    if (v >= n) return;
    float acc = bl[0];
    const float* h = &g_bufO[(size_t)v * 32];
#pragma unroll
    for (int k = 0; k < 32; k++) acc += h[k] * __ldg(&Wl[k]);
    out[v] = 1.f / (1.f + __expf(-acc));
}

extern "C" void kernel_launch(void* const* d_in, const int* in_sizes, int n_in,
                              void* d_out, int out_size) {
    const float* x = (const float*)d_in[0];
    const void* ei = (const void*)d_in[1];
    const float* W1 = (const float*)d_in[2];
    const float* b1 = (const float*)d_in[3];
    const float* W2 = (const float*)d_in[4];
    const float* b2 = (const float*)d_in[5];
    const float* W3 = (const float*)d_in[6];
    const float* b3 = (const float*)d_in[7];
    const float* Wl = (const float*)d_in[8];
    const float* bl = (const float*)d_in[9];
    float* out = (float*)d_out;

    int n = NN;

    // dynamic smem attribute (idempotent, not a stream op)
    cudaFuncSetAttribute(gemm_kernel<128, 128>, cudaFuncAttributeMaxDynamicSharedMemorySize, 81920);
    cudaFuncSetAttribute(gemm_kernel<128, 64>, cudaFuncAttributeMaxDynamicSharedMemorySize, 65536);
    cudaFuncSetAttribute(gemm_kernel<64, 32>, cudaFuncAttributeMaxDynamicSharedMemorySize, 40960);

    float* T;
    float* O;
    cudaGetSymbolAddress((void**)&T, g_bufT);
    cudaGetSymbolAddress((void**)&O, g_bufO);

    // --- edge dtype detection + degree / dinv ---
    k_detect<<<1, 32>>>(ei);
    k_init_deg<<<(NN + 255) / 256, 256>>>();
    k_count_deg<<<(EE + 255) / 256, 256>>>(ei);
    k_dinv<<<(NN + 255) / 256, 256>>>();

    // --- layer 1: 128 -> 128 ---
    {
        constexpr int K = 128, Of = 128;
        constexpr int ROWS = (256 / (Of / 4)) * 4;  // 32
        gemm_kernel<K, Of><<<(n + ROWS - 1) / ROWS, 256, 81920>>>(x, W1, T, n);
        self_kernel<Of><<<(n * (Of / 4) + 255) / 256, 256>>>(n);
        long long tot = (long long)EE * (Of / 4);
        edge_kernel<Of><<<(unsigned)((tot + 255) / 256), 256>>>(ei);
        biasrelu_kernel<Of><<<(n * (Of / 4) + 255) / 256, 256>>>(b1, n);
    }
    // --- layer 2: 128 -> 64 ---
    {
        constexpr int K = 128, Of = 64;
        constexpr int ROWS = (256 / (Of / 4)) * 4;  // 64
        gemm_kernel<K, Of><<<(n + ROWS - 1) / ROWS, 256, 65536>>>(O, W2, T, n);
        self_kernel<Of><<<(n * (Of / 4) + 255) / 256, 256>>>(n);
        long long tot = (long long)EE * (Of / 4);
        edge_kernel<Of><<<(unsigned)((tot + 255) / 256), 256>>>(ei);
        biasrelu_kernel<Of><<<(n * (Of / 4) + 255) / 256, 256>>>(b2, n);
    }
    // --- layer 3: 64 -> 32 ---
    {
        constexpr int K = 64, Of = 32;
        constexpr int ROWS = (256 / (Of / 4)) * 4;  // 128
        gemm_kernel<K, Of><<<(n + ROWS - 1) / ROWS, 256, 40960>>>(O, W3, T, n);
        self_kernel<Of><<<(n * (Of / 4) + 255) / 256, 256>>>(n);
        long long tot = (long long)EE * (Of / 4);
        edge_kernel<Of><<<(unsigned)((tot + 255) / 256), 256>>>(ei);
        biasrelu_kernel<Of><<<(n * (Of / 4) + 255) / 256, 256>>>(b3, n);
    }
    // --- head ---
    final_kernel<<<(n + 255) / 256, 256>>>(Wl, bl, out, n);
}

// round 3
// speedup vs baseline: 2.5891x; 2.5891x over previous
#include <cuda_runtime.h>
#include <math.h>

#define NN 100000
#define EE 1600000
#define SCAN_B 512
#define NB ((NN + SCAN_B - 1) / SCAN_B)

// ---------------- scratch (alloc-free: __device__ globals) ----------------
__device__ int   g_is64;
__device__ int   g_deg[NN];
__device__ int   g_cnt[NN];          // in-edge count (deg-1)
__device__ int   g_off[NN];          // CSR exclusive offsets
__device__ int   g_cur[NN];          // scatter cursors
__device__ int   g_bsum[NB];
__device__ int   g_bpre[NB];
__device__ float g_dinv[NN];
__device__ float g_selfw[NN];        // dinv^2
__device__ int   g_csr_src[EE];
__device__ float g_csr_nrm[EE];
__device__ float g_bufT[(size_t)NN * 128];  // transformed features (x @ W)
__device__ float g_bufO[(size_t)NN * 128];  // activations per layer

// ---------------- edge dtype detection ----------------
// int64 LE with values < 2^31: odd int32 words all zero. int32: odd words random ids.
__global__ void k_detect(const void* __restrict__ ei) {
    if (threadIdx.x == 0 && blockIdx.x == 0) {
        const int* w = (const int*)ei;
        int nz = 0;
        for (int i = 1; i < 256; i += 2) nz += (w[i] != 0);
        g_is64 = (nz == 0) ? 1 : 0;
    }
}

__device__ __forceinline__ int edge_at(const void* __restrict__ ei, long long i) {
    if (g_is64) return (int)((const long long*)ei)[i];
    return ((const int*)ei)[i];
}

// ---------------- degree / norm ----------------
__global__ void k_init_deg() {
    int i = blockIdx.x * blockDim.x + threadIdx.x;
    if (i < NN) g_deg[i] = 1;  // self-loop
}

__global__ void k_count_deg(const void* __restrict__ ei) {
    int i = blockIdx.x * blockDim.x + threadIdx.x;
    if (i < EE) atomicAdd(&g_deg[edge_at(ei, (long long)EE + i)], 1);
}

__global__ void k_dinv() {
    int i = blockIdx.x * blockDim.x + threadIdx.x;
    if (i < NN) {
        int dg = g_deg[i];
        float dv = rsqrtf((float)dg);
        g_dinv[i] = dv;
        g_selfw[i] = dv * dv;
        g_cnt[i] = dg - 1;
    }
}

// ---------------- CSR build: 2-level exclusive scan + scatter ----------------
__global__ void k_scan_local() {
    __shared__ int sm[SCAN_B];
    int v = blockIdx.x * SCAN_B + threadIdx.x;
    int x = (v < NN) ? g_cnt[v] : 0;
    sm[threadIdx.x] = x;
    __syncthreads();
    for (int off = 1; off < SCAN_B; off <<= 1) {
        int y = (threadIdx.x >= off) ? sm[threadIdx.x - off] : 0;
        __syncthreads();
        sm[threadIdx.x] += y;
        __syncthreads();
    }
    if (v < NN) g_off[v] = sm[threadIdx.x] - x;  // exclusive (local)
    if (threadIdx.x == SCAN_B - 1) g_bsum[blockIdx.x] = sm[SCAN_B - 1];
}

__global__ void k_scan_bsum() {
    if (threadIdx.x == 0 && blockIdx.x == 0) {
        int run = 0;
        for (int i = 0; i < NB; i++) { g_bpre[i] = run; run += g_bsum[i]; }
    }
}

__global__ void k_scan_add() {
    int v = blockIdx.x * blockDim.x + threadIdx.x;
    if (v < NN) {
        g_off[v] += g_bpre[v / SCAN_B];
        g_cur[v] = 0;
    }
}

__global__ void k_build_csr(const void* __restrict__ ei) {
    int e = blockIdx.x * blockDim.x + threadIdx.x;
    if (e >= EE) return;
    int s = edge_at(ei, e);
    int d = edge_at(ei, (long long)EE + e);
    float nrm = g_dinv[s] * g_dinv[d];
    int pos = g_off[d] + atomicAdd(&g_cur[d], 1);
    g_csr_src[pos] = s;
    g_csr_nrm[pos] = nrm;
}

// ---------------- dense transform: out[n,O] = X[n,K] @ W[K,O] ----------------
template <int K, int O>
__global__ void gemm_kernel(const float* __restrict__ X, const float* __restrict__ W,
                            float* __restrict__ out, int n) {
    constexpr int JG = O / 4;
    constexpr int RQ = 256 / JG;
    constexpr int ROWS = RQ * 4;
    extern __shared__ float sm[];
    float* Ws = sm;              // K*O
    float* Xs = sm + K * O;      // ROWS*K
    int tid = threadIdx.x;
    int row0 = blockIdx.x * ROWS;

    for (int i = tid * 4; i < K * O; i += 256 * 4)
        *(float4*)&Ws[i] = *(const float4*)&W[i];
    for (int i = tid * 4; i < ROWS * K; i += 256 * 4) {
        int r = i / K, c = i % K;
        float4 v = make_float4(0.f, 0.f, 0.f, 0.f);
        if (row0 + r < n) v = *(const float4*)&X[(size_t)(row0 + r) * K + c];
        *(float4*)&Xs[i] = v;
    }
    __syncthreads();

    int jg = tid % JG, rq = tid / JG;
    int j = jg * 4;
    float acc[4][4] = {};
    const float* xb = &Xs[(rq * 4) * K];
#pragma unroll 4
    for (int k = 0; k < K; k++) {
        float4 w = *(float4*)&Ws[k * O + j];
#pragma unroll
        for (int i = 0; i < 4; i++) {
            float xv = xb[i * K + k];
            acc[i][0] += xv * w.x;
            acc[i][1] += xv * w.y;
            acc[i][2] += xv * w.z;
            acc[i][3] += xv * w.w;
        }
    }
#pragma unroll
    for (int i = 0; i < 4; i++) {
        int r = row0 + rq * 4 + i;
        if (r < n)
            *(float4*)&out[(size_t)r * O + j] =
                make_float4(acc[i][0], acc[i][1], acc[i][2], acc[i][3]);
    }
}

// ---------------- CSR gather + self-loop + bias + relu ----------------
// G = F/4 lanes per destination node; each lane owns one float4 of the row.
template <int F>
__global__ void gather_kernel(const float* __restrict__ bias, float* __restrict__ O, int n) {
    constexpr int G = F / 4;
    int t = blockIdx.x * blockDim.x + threadIdx.x;
    int v = t / G;
    int q = t % G;
    if (v >= n) return;
    const float* T = g_bufT;

    float sw = g_selfw[v];
    float4 tv = *(const float4*)&T[(size_t)v * F + q * 4];
    float4 acc = make_float4(sw * tv.x, sw * tv.y, sw * tv.z, sw * tv.w);

    int beg = g_off[v];
    int cnt = g_cnt[v];
#pragma unroll 2
    for (int i = 0; i < cnt; i++) {
        int s = g_csr_src[beg + i];        // warp-broadcast
        float nrm = g_csr_nrm[beg + i];    // warp-broadcast
        float4 x = *(const float4*)&T[(size_t)s * F + q * 4];
        acc.x += nrm * x.x; acc.y += nrm * x.y;
        acc.z += nrm * x.z; acc.w += nrm * x.w;
    }
    float4 b = *(const float4*)&bias[q * 4];
    acc.x = fmaxf(acc.x + b.x, 0.f);
    acc.y = fmaxf(acc.y + b.y, 0.f);
    acc.z = fmaxf(acc.z + b.z, 0.f);
    acc.w = fmaxf(acc.w + b.w, 0.f);
    *(float4*)&O[(size_t)v * F + q * 4] = acc;
}

// ---------------- layer-3 gather fused with logistic head ----------------
__global__ void gather_head_kernel(const float* __restrict__ bias,
                                   const float* __restrict__ Wl,
                                   const float* __restrict__ bl,
                                   float* __restrict__ out, int n) {
    constexpr int F = 32, G = 8;
    int t = blockIdx.x * blockDim.x + threadIdx.x;
    int v = t / G;
    int q = t % G;
    if (v >= n) return;
    const float* T = g_bufT;

    float sw = g_selfw[v];
    float4 tv = *(const float4*)&T[(size_t)v * F + q * 4];
    float4 acc = make_float4(sw * tv.x, sw * tv.y, sw * tv.z, sw * tv.w);

    int beg = g_off[v];
    int cnt = g_cnt[v];
#pragma unroll 2
    for (int i = 0; i < cnt; i++) {
        int s = g_csr_src[beg + i];
        float nrm = g_csr_nrm[beg + i];
        float4 x = *(const float4*)&T[(size_t)s * F + q * 4];
        acc.x += nrm * x.x; acc.y += nrm * x.y;
        acc.z += nrm * x.z; acc.w += nrm * x.w;
    }
    float4 b = *(const float4*)&bias[q * 4];
    acc.x = fmaxf(acc.x + b.x, 0.f);
    acc.y = fmaxf(acc.y + b.y, 0.f);
    acc.z = fmaxf(acc.z + b.z, 0.f);
    acc.w = fmaxf(acc.w + b.w, 0.f);

    float4 w = *(const float4*)&Wl[q * 4];
    float p = acc.x * w.x + acc.y * w.y + acc.z * w.z + acc.w * w.w;
#pragma unroll
    for (int off = 4; off; off >>= 1) p += __shfl_down_sync(0xffffffffu, p, off, G);
    if (q == 0) out[v] = 1.f / (1.f + __expf(-(p + bl[0])));
}

extern "C" void kernel_launch(void* const* d_in, const int* in_sizes, int n_in,
                              void* d_out, int out_size) {
    const float* x = (const float*)d_in[0];
    const void* ei = (const void*)d_in[1];
    const float* W1 = (const float*)d_in[2];
    const float* b1 = (const float*)d_in[3];
    const float* W2 = (const float*)d_in[4];
    const float* b2 = (const float*)d_in[5];
    const float* W3 = (const float*)d_in[6];
    const float* b3 = (const float*)d_in[7];
    const float* Wl = (const float*)d_in[8];
    const float* bl = (const float*)d_in[9];
    float* out = (float*)d_out;
    int n = NN;

    cudaFuncSetAttribute(gemm_kernel<128, 128>, cudaFuncAttributeMaxDynamicSharedMemorySize, 81920);
    cudaFuncSetAttribute(gemm_kernel<128, 64>, cudaFuncAttributeMaxDynamicSharedMemorySize, 65536);
    cudaFuncSetAttribute(gemm_kernel<64, 32>, cudaFuncAttributeMaxDynamicSharedMemorySize, 40960);

    float* T;
    float* O;
    cudaGetSymbolAddress((void**)&T, g_bufT);
    cudaGetSymbolAddress((void**)&O, g_bufO);

    // --- preprocessing: dtype, degrees, norms, CSR ---
    k_detect<<<1, 32>>>(ei);
    k_init_deg<<<(NN + 255) / 256, 256>>>();
    k_count_deg<<<(EE + 255) / 256, 256>>>(ei);
    k_dinv<<<(NN + 255) / 256, 256>>>();
    k_scan_local<<<NB, SCAN_B>>>();
    k_scan_bsum<<<1, 32>>>();
    k_scan_add<<<(NN + 255) / 256, 256>>>();
    k_build_csr<<<(EE + 255) / 256, 256>>>(ei);

    // --- layer 1: 128 -> 128 ---
    {
        constexpr int K = 128, Of = 128, ROWS = (256 / (Of / 4)) * 4;
        gemm_kernel<K, Of><<<(n + ROWS - 1) / ROWS, 256, 81920>>>(x, W1, T, n);
        gather_kernel<Of><<<(n * (Of / 4) + 255) / 256, 256>>>(b1, O, n);
    }
    // --- layer 2: 128 -> 64 ---
    {
        constexpr int K = 128, Of = 64, ROWS = (256 / (Of / 4)) * 4;
        gemm_kernel<K, Of><<<(n + ROWS - 1) / ROWS, 256, 65536>>>(O, W2, T, n);
        gather_kernel<Of><<<(n * (Of / 4) + 255) / 256, 256>>>(b2, O, n);
    }
    // --- layer 3: 64 -> 32 + head ---
    {
        constexpr int K = 64, Of = 32, ROWS = (256 / (Of / 4)) * 4;
        gemm_kernel<K, Of><<<(n + ROWS - 1) / ROWS, 256, 40960>>>(O, W3, T, n);
        gather_head_kernel<<<(n * 8 + 255) / 256, 256>>>(b3, Wl, bl, out, n);
    }
}